// round 2
// baseline (speedup 1.0000x reference)
#include <cuda_runtime.h>
#include <cstddef>

// Problem constants
#define BATCH   16
#define IN_CH   2
#define FDIM    2048
#define TDIM    1024
#define NBANDS  64
#define BANDSZ  32      // FDIM / NBANDS
#define EMB     128

#define THREADS 256     // each thread owns 4 consecutive t (float4) in phase 1

__global__ __launch_bounds__(THREADS)
void bandsplit_kernel(const float* __restrict__ x,
                      const float* __restrict__ W,
                      const float* __restrict__ bias,
                      float* __restrict__ out)
{
    // band means for full T, both channels: 2 * 1024 floats = 8 KB
    __shared__ float xm0[TDIM];
    __shared__ float xm1[TDIM];

    const int g = blockIdx.x;           // 0 .. 1023
    const int n = g & 63;               // band
    const int b = g >> 6;               // batch
    const int tid = threadIdx.x;

    // ---------------- Phase 1: band mean over 32 f-rows, both channels ------
    // x index: ((b*IN_CH + c)*FDIM + f)*TDIM + t ; thread owns t = tid*4 .. +3
    const size_t ft = (size_t)FDIM * TDIM;
    const float4* xp0 = (const float4*)(x + (size_t)b * IN_CH * ft
                                          + (size_t)(n * BANDSZ) * TDIM)
                        + tid;                          // float4 index within row
    const float4* xp1 = xp0 + ft / 4;
    const int row4 = TDIM / 4;                          // 256 float4 per f-row

    float4 s0 = make_float4(0.f, 0.f, 0.f, 0.f);
    float4 s1 = make_float4(0.f, 0.f, 0.f, 0.f);
    #pragma unroll
    for (int f = 0; f < BANDSZ; f++) {
        const float4 v = __ldcs(xp0 + (size_t)f * row4);
        s0.x += v.x; s0.y += v.y; s0.z += v.z; s0.w += v.w;
    }
    #pragma unroll
    for (int f = 0; f < BANDSZ; f++) {
        const float4 v = __ldcs(xp1 + (size_t)f * row4);
        s1.x += v.x; s1.y += v.y; s1.z += v.z; s1.w += v.w;
    }

    const float inv = 1.f / BANDSZ;
    const int t4 = tid * 4;
    xm0[t4 + 0] = s0.x * inv;  xm0[t4 + 1] = s0.y * inv;
    xm0[t4 + 2] = s0.z * inv;  xm0[t4 + 3] = s0.w * inv;
    xm1[t4 + 0] = s1.x * inv;  xm1[t4 + 1] = s1.y * inv;
    xm1[t4 + 2] = s1.z * inv;  xm1[t4 + 3] = s1.w * inv;
    __syncthreads();

    // ---------------- Phase 2: project to EMB and write ---------------------
    // warp = one t-row per iteration; lane covers 4 consecutive emb elements.
    const int e4   = (tid & 31) * 4;
    const int trow = tid >> 5;          // 0..7

    const float4 w0 = *(const float4*)(W + ((size_t)n * IN_CH + 0) * EMB + e4);
    const float4 w1 = *(const float4*)(W + ((size_t)n * IN_CH + 1) * EMB + e4);
    const float4 bb = *(const float4*)(bias + (size_t)n * EMB + e4);

    // out index: ((b*NBANDS + n)*TDIM + t)*EMB + e
    float4* op = (float4*)(out + (((size_t)b * NBANDS + n) * TDIM) * EMB + e4);

    #pragma unroll 8
    for (int i = 0; i < TDIM / 8; i++) {
        const int t = trow + i * 8;
        const float m0 = xm0[t];        // warp-uniform smem broadcast
        const float m1 = xm1[t];
        float4 r;
        r.x = fmaf(m0, w0.x, fmaf(m1, w1.x, bb.x));
        r.y = fmaf(m0, w0.y, fmaf(m1, w1.y, bb.y));
        r.z = fmaf(m0, w0.z, fmaf(m1, w1.z, bb.z));
        r.w = fmaf(m0, w0.w, fmaf(m1, w1.w, bb.w));
        __stcs(op + (size_t)t * (EMB / 4), r);
    }
}

extern "C" void kernel_launch(void* const* d_in, const int* in_sizes, int n_in,
                              void* d_out, int out_size)
{
    const float* x    = (const float*)d_in[0];
    const float* W    = (const float*)d_in[1];
    const float* bias = (const float*)d_in[2];
    float* out        = (float*)d_out;

    const int grid = BATCH * NBANDS;    // 1024 blocks -> single wave on 148 SMs
    bandsplit_kernel<<<grid, THREADS>>>(x, W, bias, out);
}

// round 3
// speedup vs baseline: 1.0735x; 1.0735x over previous
#include <cuda_runtime.h>
#include <cstddef>

// Problem constants
#define BATCH   16
#define IN_CH   2
#define FDIM    2048
#define TDIM    1024
#define NBANDS  64
#define BANDSZ  32      // FDIM / NBANDS
#define EMB     128

// Intermediate band means: [b][n][c][t]  (float), 16*64*2*1024 = 2M floats = 8 MB
__device__ float g_xmean[BATCH * NBANDS * IN_CH * TDIM];

// ---------------------------------------------------------------------------
// K1: pure-read reduction. One block per (b, c, n). 256 threads, each owns one
// float4 column of t, sums 32 f-rows with streaming loads.
// ---------------------------------------------------------------------------
__global__ __launch_bounds__(256)
void reduce_kernel(const float* __restrict__ x)
{
    const int g = blockIdx.x;           // 0 .. 2047
    const int n = g & 63;
    const int c = (g >> 6) & 1;
    const int b = g >> 7;
    const int tid = threadIdx.x;        // float4 column: t = tid*4

    // x index: ((b*IN_CH + c)*FDIM + f)*TDIM + t
    const float4* xp = (const float4*)(x
        + (((size_t)(b * IN_CH + c)) * FDIM + (size_t)n * BANDSZ) * TDIM)
        + tid;
    const int row4 = TDIM / 4;          // 256 float4 per f-row

    float4 s = make_float4(0.f, 0.f, 0.f, 0.f);
    #pragma unroll
    for (int f = 0; f < BANDSZ; f++) {
        const float4 v = __ldcs(xp + (size_t)f * row4);
        s.x += v.x; s.y += v.y; s.z += v.z; s.w += v.w;
    }
    const float inv = 1.f / BANDSZ;
    s.x *= inv; s.y *= inv; s.z *= inv; s.w *= inv;

    // xmean layout [b][n][c][t] -> float4 index ((b*NBANDS + n)*IN_CH + c)*256 + tid
    float4* mp = (float4*)g_xmean
               + ((size_t)(b * NBANDS + n) * IN_CH + c) * row4 + tid;
    *mp = s;                            // normal store: keep resident in L2
}

// ---------------------------------------------------------------------------
// K2: pure-write projection. One block per (b, n, t-chunk of 256). Reads 2 KB
// of means (L2-hot), writes 128 KB of output, fully coalesced float4.
// ---------------------------------------------------------------------------
__global__ __launch_bounds__(256)
void project_kernel(const float* __restrict__ W,
                    const float* __restrict__ bias,
                    float* __restrict__ out)
{
    __shared__ float xm0[256];
    __shared__ float xm1[256];

    const int g  = blockIdx.x;          // 0 .. 4095
    const int tc = g & 3;
    const int n  = (g >> 2) & 63;
    const int b  = g >> 8;
    const int t0 = tc * 256;
    const int tid = threadIdx.x;

    // Load means for this chunk: 2 channels x 256 floats = 128 float4
    if (tid < 128) {
        const int c   = tid >> 6;       // 0..1
        const int col = tid & 63;       // float4 col within chunk
        const float4 v = *((const float4*)g_xmean
            + ((size_t)(b * NBANDS + n) * IN_CH + c) * (TDIM / 4)
            + (t0 / 4) + col);
        float* dst = (c == 0 ? xm0 : xm1) + col * 4;
        dst[0] = v.x; dst[1] = v.y; dst[2] = v.z; dst[3] = v.w;
    }

    const int e4   = (tid & 31) * 4;
    const int trow = tid >> 5;

    const float4 w0 = *(const float4*)(W + ((size_t)n * IN_CH + 0) * EMB + e4);
    const float4 w1 = *(const float4*)(W + ((size_t)n * IN_CH + 1) * EMB + e4);
    const float4 bb = *(const float4*)(bias + (size_t)n * EMB + e4);

    __syncthreads();

    // out index: ((b*NBANDS + n)*TDIM + t)*EMB + e
    float4* op = (float4*)(out + (((size_t)b * NBANDS + n) * TDIM + t0) * EMB + e4);

    #pragma unroll 8
    for (int i = 0; i < 256 / 8; i++) {
        const int t = trow + i * 8;
        const float m0 = xm0[t];        // warp-uniform smem broadcast
        const float m1 = xm1[t];
        float4 r;
        r.x = fmaf(m0, w0.x, fmaf(m1, w1.x, bb.x));
        r.y = fmaf(m0, w0.y, fmaf(m1, w1.y, bb.y));
        r.z = fmaf(m0, w0.z, fmaf(m1, w1.z, bb.z));
        r.w = fmaf(m0, w0.w, fmaf(m1, w1.w, bb.w));
        __stcs(op + (size_t)t * (EMB / 4), r);
    }
}

extern "C" void kernel_launch(void* const* d_in, const int* in_sizes, int n_in,
                              void* d_out, int out_size)
{
    const float* x    = (const float*)d_in[0];
    const float* W    = (const float*)d_in[1];
    const float* bias = (const float*)d_in[2];
    float* out        = (float*)d_out;

    reduce_kernel<<<BATCH * IN_CH * NBANDS, 256>>>(x);                 // 2048 blocks
    project_kernel<<<BATCH * NBANDS * (TDIM / 256), 256>>>(W, bias, out); // 4096 blocks
}

// round 4
// speedup vs baseline: 1.1114x; 1.0353x over previous
#include <cuda_runtime.h>
#include <cstddef>

// Problem constants
#define BATCH   16
#define IN_CH   2
#define FDIM    2048
#define TDIM    1024
#define NBANDS  64
#define BANDSZ  32      // FDIM / NBANDS
#define EMB     128

#define T_CHUNK 256
#define THREADS 256

__global__ __launch_bounds__(THREADS)
void bandsplit_kernel(const float* __restrict__ x,
                      const float* __restrict__ W,
                      const float* __restrict__ bias,
                      float* __restrict__ out)
{
    // partial sums: [ch][fgroup][t4col] as float4 -> 2*4*64*16B = 8 KB
    __shared__ float4 part[IN_CH][4][T_CHUNK / 4];
    // final means: [ch][t] -> 2 KB
    __shared__ float xm[IN_CH][T_CHUNK];

    const int g  = blockIdx.x;
    const int tc = g & 3;               // t-chunk index (TDIM / T_CHUNK = 4)
    const int n  = (g >> 2) & 63;       // band
    const int b  = g >> 8;              // batch
    const int t0 = tc * T_CHUNK;
    const int tid = threadIdx.x;

    // ---------------- Phase 1: band sum, float4, 4-way f-split --------------
    // thread owns float4 column t4 (64 cols = 256 t) and f-group fg (8 rows).
    const int t4 = tid & 63;
    const int fg = tid >> 6;            // 0..3

    const size_t ft = (size_t)FDIM * TDIM;
    const int row4 = TDIM / 4;          // 256 float4 per f-row

    const float4* xp0 = (const float4*)(x + (size_t)b * IN_CH * ft
                                          + ((size_t)(n * BANDSZ) + fg * 8) * TDIM
                                          + t0) + t4;
    const float4* xp1 = xp0 + ft / 4;

    float4 s0 = make_float4(0.f, 0.f, 0.f, 0.f);
    float4 s1 = make_float4(0.f, 0.f, 0.f, 0.f);
    #pragma unroll
    for (int f = 0; f < 8; f++) {
        const float4 v = __ldcs(xp0 + (size_t)f * row4);
        s0.x += v.x; s0.y += v.y; s0.z += v.z; s0.w += v.w;
    }
    #pragma unroll
    for (int f = 0; f < 8; f++) {
        const float4 v = __ldcs(xp1 + (size_t)f * row4);
        s1.x += v.x; s1.y += v.y; s1.z += v.z; s1.w += v.w;
    }
    part[0][fg][t4] = s0;
    part[1][fg][t4] = s1;
    __syncthreads();

    // Cross-f reduction: 128 threads combine the 4 partials per (c, t4).
    if (tid < 128) {
        const int c  = tid >> 6;
        const int tc4 = tid & 63;
        const float4 p0 = part[c][0][tc4];
        const float4 p1 = part[c][1][tc4];
        const float4 p2 = part[c][2][tc4];
        const float4 p3 = part[c][3][tc4];
        const float inv = 1.f / BANDSZ;
        xm[c][tc4 * 4 + 0] = (p0.x + p1.x + p2.x + p3.x) * inv;
        xm[c][tc4 * 4 + 1] = (p0.y + p1.y + p2.y + p3.y) * inv;
        xm[c][tc4 * 4 + 2] = (p0.z + p1.z + p2.z + p3.z) * inv;
        xm[c][tc4 * 4 + 3] = (p0.w + p1.w + p2.w + p3.w) * inv;
    }

    // Load weights while the reduction settles (independent of smem).
    const int e4   = (tid & 31) * 4;
    const int trow = tid >> 5;

    const float4 w0 = *(const float4*)(W + ((size_t)n * IN_CH + 0) * EMB + e4);
    const float4 w1 = *(const float4*)(W + ((size_t)n * IN_CH + 1) * EMB + e4);
    const float4 bb = *(const float4*)(bias + (size_t)n * EMB + e4);

    __syncthreads();

    // ---------------- Phase 2: project to EMB and write ---------------------
    // out index: ((b*NBANDS + n)*TDIM + t)*EMB + e
    float4* op = (float4*)(out + (((size_t)b * NBANDS + n) * TDIM + t0) * EMB + e4);

    #pragma unroll 8
    for (int i = 0; i < T_CHUNK / 8; i++) {
        const int t = trow + i * 8;
        const float m0 = xm[0][t];      // warp-uniform smem broadcast
        const float m1 = xm[1][t];
        float4 r;
        r.x = fmaf(m0, w0.x, fmaf(m1, w1.x, bb.x));
        r.y = fmaf(m0, w0.y, fmaf(m1, w1.y, bb.y));
        r.z = fmaf(m0, w0.z, fmaf(m1, w1.z, bb.z));
        r.w = fmaf(m0, w0.w, fmaf(m1, w1.w, bb.w));
        __stcs(op + (size_t)t * (EMB / 4), r);
    }
}

extern "C" void kernel_launch(void* const* d_in, const int* in_sizes, int n_in,
                              void* d_out, int out_size)
{
    const float* x    = (const float*)d_in[0];
    const float* W    = (const float*)d_in[1];
    const float* bias = (const float*)d_in[2];
    float* out        = (float*)d_out;

    const int grid = BATCH * NBANDS * (TDIM / T_CHUNK);  // 4096
    bandsplit_kernel<<<grid, THREADS>>>(x, W, bias, out);
}